// round 2
// baseline (speedup 1.0000x reference)
#include <cuda_runtime.h>
#include <float.h>

#define Bb 2
#define Hh 16
#define Ss 2048
#define Dd 64
#define BM 128     // query rows per CTA (== blockDim.x, 1 row/thread)
#define BN 16      // key tile

// ---------------------------------------------------------------------------
// Mask dtype handling: jax bool may arrive as 1-byte bool or as int32.
// Detect by scanning the mask as u32 words (covers the whole 4096-byte
// byte-bool buffer): random 0/1 bytes make some word >1 with prob
// 1-(1/8)^1024. If every word is in {0,1}, the buffer is int32 {0,1}.
// ---------------------------------------------------------------------------
__device__ int   g_mask_is_i32;
__device__ float g_maskadd[Bb * Ss];   // 0.0f if key valid, -FLT_MAX if masked

__global__ void detect_mask_kernel(const unsigned int* __restrict__ mask_w) {
    __shared__ int bad;
    if (threadIdx.x == 0) bad = 0;
    __syncthreads();
    for (int idx = threadIdx.x; idx < (Bb * Ss) / 4; idx += blockDim.x) {
        if (mask_w[idx] > 1u) bad = 1;
    }
    __syncthreads();
    if (threadIdx.x == 0) g_mask_is_i32 = bad ? 0 : 1;
}

__global__ void expand_mask_kernel(const void* __restrict__ mask) {
    int idx = blockIdx.x * blockDim.x + threadIdx.x;
    if (idx >= Bb * Ss) return;
    int is32 = g_mask_is_i32;
    int mval = is32 ? ((const int*)mask)[idx]
                    : (int)((const unsigned char*)mask)[idx];
    g_maskadd[idx] = mval ? 0.0f : -FLT_MAX;
}

// ---------------------------------------------------------------------------
// Flash-attention style: each thread owns one query row. K/V tiles (BN x 64)
// double-buffered in smem, read back as warp-uniform broadcast LDS.128
// (conflict-free). q row and output accumulator in registers. Online softmax.
// ---------------------------------------------------------------------------
__global__ void __launch_bounds__(BM)
attn_kernel(const float* __restrict__ q,
            const float* __restrict__ k,
            const float* __restrict__ v,
            const float* __restrict__ taus,
            const float* __restrict__ bias,
            float* __restrict__ out)
{
    const int tid   = threadIdx.x;
    const int itile = blockIdx.x;   // S/BM = 16
    const int h     = blockIdx.y;   // 16
    const int b     = blockIdx.z;   // 2

    const int i = itile * BM + tid;            // this thread's query row
    const float tau   = taus[h];
    const float scale = 0.125f;                // 1/sqrt(64)

    const int plane = (b * Hh + h) * Ss;       // (b,h) plane row offset

    __shared__ float4 ks[2][BN * (Dd / 4)];    // double-buffered, 8 KB
    __shared__ float4 vs[2][BN * (Dd / 4)];    //                  8 KB
    __shared__ float  smask[Ss];               // additive mask row, 8 KB

    // stage mask row for this batch into smem once
    {
        const float* madd = g_maskadd + b * Ss;
        for (int x = tid; x < Ss; x += BM) smask[x] = madd[x];
    }

    // load q row into registers
    float4 qr[Dd / 4];
    {
        const float4* qrow = (const float4*)(q + (size_t)(plane + i) * Dd);
#pragma unroll
        for (int d4 = 0; d4 < Dd / 4; d4++) qr[d4] = qrow[d4];
    }

    float4 o[Dd / 4];
#pragma unroll
    for (int d4 = 0; d4 < Dd / 4; d4++) o[d4] = make_float4(0.f, 0.f, 0.f, 0.f);
    float m = -FLT_MAX;
    float l = 0.f;

    const float4* kbase = (const float4*)(k + (size_t)plane * Dd);
    const float4* vbase = (const float4*)(v + (size_t)plane * Dd);
    const float*  brow  = bias + ((size_t)b * Ss + i) * Ss;

    // prologue: fill buffer 0 with tile j0=0
    {
        ks[0][tid]      = kbase[tid];
        ks[0][tid + BM] = kbase[tid + BM];
        vs[0][tid]      = vbase[tid];
        vs[0][tid + BM] = vbase[tid + BM];
    }
    __syncthreads();

    const int NTILES = Ss / BN;   // 128
    for (int t = 0; t < NTILES; t++) {
        const int j0  = t * BN;
        const int cur = t & 1;

        // prefetch next tile into the other buffer (no barrier needed before
        // the stores: buffer `nxt` was last READ two iterations ago and a
        // __syncthreads has happened since)
        if (t + 1 < NTILES) {
            const int nxt  = cur ^ 1;
            const int base = (t + 1) * BN * (Dd / 4);   // float4 index
            ks[nxt][tid]      = kbase[base + tid];
            ks[nxt][tid + BM] = kbase[base + tid + BM];
            vs[nxt][tid]      = vbase[base + tid];
            vs[nxt][tid + BM] = vbase[base + tid + BM];
        }

        // ---- scores: s[j] = q . k_j ----
        float s[BN];
#pragma unroll
        for (int j = 0; j < BN; j++) {
            float acc = 0.f;
#pragma unroll
            for (int d4 = 0; d4 < Dd / 4; d4++) {
                float4 kk = ks[cur][j * (Dd / 4) + d4];
                acc += qr[d4].x * kk.x;
                acc += qr[d4].y * kk.y;
                acc += qr[d4].z * kk.z;
                acc += qr[d4].w * kk.w;
            }
            s[j] = acc;
        }

        // ---- bias tile (per-row, contiguous 64B chunks) ----
        float bv[BN];
        {
            const float4* bsrc = (const float4*)(brow + j0);
#pragma unroll
            for (int jb = 0; jb < BN / 4; jb++) {
                float4 tt = bsrc[jb];
                bv[4 * jb + 0] = tt.x;
                bv[4 * jb + 1] = tt.y;
                bv[4 * jb + 2] = tt.z;
                bv[4 * jb + 3] = tt.w;
            }
        }

        // ---- mask + bias + running max ----
        float mnew = m;
#pragma unroll
        for (int j = 0; j < BN; j++) {
            // masked: s*scale + (-FLT_MAX) rounds to -FLT_MAX (matches ref's
            // masked_fill-then-subtract: -FLT_MAX - tau*b == -FLT_MAX in fp32)
            float sv = s[j] * scale + smask[j0 + j];
            sv -= tau * bv[j];
            s[j] = sv;
            mnew = fmaxf(mnew, sv);
        }

        // ---- online softmax rescale ----
        float alpha = __expf(m - mnew);
        m = mnew;
        l *= alpha;
#pragma unroll
        for (int d4 = 0; d4 < Dd / 4; d4++) {
            o[d4].x *= alpha; o[d4].y *= alpha;
            o[d4].z *= alpha; o[d4].w *= alpha;
        }
#pragma unroll
        for (int j = 0; j < BN; j++) {
            float p = __expf(s[j] - mnew);
            s[j] = p;
            l += p;
        }

        // ---- accumulate P @ V ----
#pragma unroll
        for (int d4 = 0; d4 < Dd / 4; d4++) {
            float4 acc = o[d4];
#pragma unroll
            for (int j = 0; j < BN; j++) {
                float4 vv = vs[cur][j * (Dd / 4) + d4];
                acc.x += s[j] * vv.x;
                acc.y += s[j] * vv.y;
                acc.z += s[j] * vv.z;
                acc.w += s[j] * vv.w;
            }
            o[d4] = acc;
        }

        __syncthreads();   // next-tile stores (already issued) become visible
    }

    // ---- normalize + write ----
    float inv = 1.0f / l;
    float4* orow = (float4*)(out + (size_t)(plane + i) * Dd);
#pragma unroll
    for (int d4 = 0; d4 < Dd / 4; d4++) {
        float4 tt = o[d4];
        tt.x *= inv; tt.y *= inv; tt.z *= inv; tt.w *= inv;
        orow[d4] = tt;
    }
}

extern "C" void kernel_launch(void* const* d_in, const int* in_sizes, int n_in,
                              void* d_out, int out_size) {
    const float* q    = (const float*)d_in[0];
    const float* k    = (const float*)d_in[1];
    const float* v    = (const float*)d_in[2];
    const void*  mask = d_in[3];
    const float* taus = (const float*)d_in[4];
    const float* bias = (const float*)d_in[5];
    float*       out  = (float*)d_out;
    (void)in_sizes; (void)n_in; (void)out_size;

    detect_mask_kernel<<<1, 256>>>((const unsigned int*)mask);
    expand_mask_kernel<<<(Bb * Ss + 255) / 256, 256>>>(mask);

    dim3 grid(Ss / BM, Hh, Bb);
    attn_kernel<<<grid, BM>>>(q, k, v, taus, bias, out);
}

// round 4
// speedup vs baseline: 2.2056x; 2.2056x over previous
#include <cuda_runtime.h>
#include <float.h>
#include <stdint.h>

#define Bb 2
#define Hh 16
#define Ss 2048
#define Dd 64
#define BM 128          // query rows per CTA (8 warps x 16 rows)
#define BN 64           // key tile
#define NTHREADS 256
#define NTILES (Ss / BN)   // 32

// ---- shared memory layout (float offsets) ----
#define OFF_MASK 0                      // [2048] additive mask row
#define OFF_K    2048                   // [64][68]  K tile (padded)
#define OFF_V    (OFF_K + 64 * 68)      // [64][72]  V tile (padded)
#define OFF_P    (OFF_V + 64 * 72)      // [128][68] P tile / Q staging
#define SMEM_FLOATS (OFF_P + 128 * 68)  // 19712 floats = 78848 B
#define KST 68
#define VST 72
#define PST 68

// ---------------------------------------------------------------------------
// tf32 helpers
// ---------------------------------------------------------------------------
__device__ __forceinline__ float rna(float x) {
    uint32_t u;
    asm("cvt.rna.tf32.f32 %0, %1;" : "=r"(u) : "f"(x));
    return __uint_as_float(u);
}
__device__ __forceinline__ float4 rna4(float4 t) {
    return make_float4(rna(t.x), rna(t.y), rna(t.z), rna(t.w));
}

// D += A*B, m16n8k8 tf32. d: f32x4, a: tf32x4, b: tf32x2 (PTX fragment layouts)
__device__ __forceinline__ void mma8(float* d, const uint32_t* a,
                                     uint32_t b0, uint32_t b1) {
    asm volatile(
        "mma.sync.aligned.m16n8k8.row.col.f32.tf32.tf32.f32 "
        "{%0,%1,%2,%3},{%4,%5,%6,%7},{%8,%9},{%0,%1,%2,%3};"
        : "+f"(d[0]), "+f"(d[1]), "+f"(d[2]), "+f"(d[3])
        : "r"(a[0]), "r"(a[1]), "r"(a[2]), "r"(a[3]), "r"(b0), "r"(b1));
}

// ---------------------------------------------------------------------------
// Mask prepass (jax bool may be byte-bool or int32; detect then expand)
// ---------------------------------------------------------------------------
__device__ int   g_mask_is_i32;
__device__ float g_maskadd[Bb * Ss];

__global__ void detect_mask_kernel(const unsigned int* __restrict__ mask_w) {
    __shared__ int bad;
    if (threadIdx.x == 0) bad = 0;
    __syncthreads();
    for (int idx = threadIdx.x; idx < (Bb * Ss) / 4; idx += blockDim.x)
        if (mask_w[idx] > 1u) bad = 1;
    __syncthreads();
    if (threadIdx.x == 0) g_mask_is_i32 = bad ? 0 : 1;
}
__global__ void expand_mask_kernel(const void* __restrict__ mask) {
    int idx = blockIdx.x * blockDim.x + threadIdx.x;
    if (idx >= Bb * Ss) return;
    int mval = g_mask_is_i32 ? ((const int*)mask)[idx]
                             : (int)((const unsigned char*)mask)[idx];
    g_maskadd[idx] = mval ? 0.0f : -FLT_MAX;
}

// ---------------------------------------------------------------------------
// Main attention kernel
// ---------------------------------------------------------------------------
__global__ void __launch_bounds__(NTHREADS, 1)
attn_kernel(const float* __restrict__ q,
            const float* __restrict__ k,
            const float* __restrict__ v,
            const float* __restrict__ taus,
            const float* __restrict__ bias,
            float* __restrict__ out)
{
    extern __shared__ float s[];

    const int tid  = threadIdx.x;
    const int wid  = tid >> 5;
    const int lane = tid & 31;
    const int g    = lane >> 2;    // groupID (row within fragment)
    const int tig  = lane & 3;     // threadID_in_group

    const int itile = blockIdx.x;
    const int h     = blockIdx.y;
    const int b     = blockIdx.z;

    const int   plane = (b * Hh + h) * Ss;
    const float tau   = taus[h];
    const int   rowb  = wid * 16;              // warp's first local row

    // ---- stage mask row + Q tile (tf32-rounded) ----
    {
        const float* madd = g_maskadd + b * Ss;
        for (int x = tid; x < Ss; x += NTHREADS) s[OFF_MASK + x] = madd[x];

        const float4* qsrc = (const float4*)(q + (size_t)(plane + itile * BM) * Dd);
        for (int idx = tid; idx < BM * (Dd / 4); idx += NTHREADS) {
            int row = idx >> 4, c4 = idx & 15;
            *(float4*)&s[OFF_P + row * PST + c4 * 4] = rna4(qsrc[idx]);
        }
    }
    __syncthreads();

    // ---- load Q fragments: qf[k0] covers cols [8k0, 8k0+8) of warp's rows ----
    uint32_t qf[8][4];
#pragma unroll
    for (int k0 = 0; k0 < 8; k0++) {
        const float* pr0 = &s[OFF_P + (rowb + g) * PST + k0 * 8];
        const float* pr1 = pr0 + 8 * PST;
        qf[k0][0] = __float_as_uint(pr0[tig]);
        qf[k0][1] = __float_as_uint(pr1[tig]);
        qf[k0][2] = __float_as_uint(pr0[tig + 4]);
        qf[k0][3] = __float_as_uint(pr1[tig + 4]);
    }

    float oacc[8][4];
#pragma unroll
    for (int n0 = 0; n0 < 8; n0++)
#pragma unroll
        for (int x = 0; x < 4; x++) oacc[n0][x] = 0.f;
    float l0 = 0.f, l1 = 0.f;

    const float4* ksrc = (const float4*)(k + (size_t)plane * Dd);
    const float4* vsrc = (const float4*)(v + (size_t)plane * Dd);
    const int qg0 = itile * BM + rowb + g;
    const float* brow0 = bias + ((size_t)b * Ss + qg0) * Ss;
    const float* brow1 = brow0 + 8 * Ss;

    for (int t = 0; t < NTILES; t++) {
        const int j0 = t * BN;

        // ---- stage K,V tiles (tf32-rounded, padded strides) ----
        for (int idx = tid; idx < BN * (Dd / 4); idx += NTHREADS) {
            int row = idx >> 4, c4 = idx & 15;
            *(float4*)&s[OFF_K + row * KST + c4 * 4] = rna4(ksrc[j0 * 16 + idx]);
            *(float4*)&s[OFF_V + row * VST + c4 * 4] = rna4(vsrc[j0 * 16 + idx]);
        }
        __syncthreads();

        // ---- MMA1: S(16x64) = Q(16x64) @ K^T ----
        float sacc[8][4];
#pragma unroll
        for (int n0 = 0; n0 < 8; n0++) {
#pragma unroll
            for (int x = 0; x < 4; x++) sacc[n0][x] = 0.f;
            const float* krow = &s[OFF_K + (n0 * 8 + g) * KST];
#pragma unroll
            for (int k0 = 0; k0 < 8; k0++) {
                uint32_t b0 = __float_as_uint(krow[k0 * 8 + tig]);
                uint32_t b1 = __float_as_uint(krow[k0 * 8 + tig + 4]);
                mma8(sacc[n0], qf[k0], b0, b1);
            }
        }

        // ---- softmax: scale + mask + tau*bias + exp; write P to smem ----
#pragma unroll
        for (int n0 = 0; n0 < 8; n0++) {
            const int jl  = n0 * 8 + tig * 2;
            const int jgl = j0 + jl;
            float2 mk  = *(const float2*)&s[OFF_MASK + jgl];
            float2 bi0 = *(const float2*)&brow0[jgl];
            float2 bi1 = *(const float2*)&brow1[jgl];
            // masked: x*0.125 + (-FLT_MAX) -> -FLT_MAX; minus tau*bias stays
            // -FLT_MAX (no -inf); __expf(-FLT_MAX) == 0 exactly.
            float p00 = __expf(fmaf(sacc[n0][0], 0.125f, mk.x) - tau * bi0.x);
            float p01 = __expf(fmaf(sacc[n0][1], 0.125f, mk.y) - tau * bi0.y);
            float p10 = __expf(fmaf(sacc[n0][2], 0.125f, mk.x) - tau * bi1.x);
            float p11 = __expf(fmaf(sacc[n0][3], 0.125f, mk.y) - tau * bi1.y);
            l0 += p00 + p01;
            l1 += p10 + p11;
            *(float2*)&s[OFF_P + (rowb + g) * PST + jl]     = make_float2(rna(p00), rna(p01));
            *(float2*)&s[OFF_P + (rowb + g + 8) * PST + jl] = make_float2(rna(p10), rna(p11));
        }
        __syncwarp();   // warp reads back only its own 16 P rows

        // ---- MMA2: O(16x64) += P(16x64) @ V(64x64) ----
#pragma unroll
        for (int k0 = 0; k0 < 8; k0++) {
            const float* pr0 = &s[OFF_P + (rowb + g) * PST + k0 * 8];
            const float* pr1 = pr0 + 8 * PST;
            uint32_t a[4];
            a[0] = __float_as_uint(pr0[tig]);
            a[1] = __float_as_uint(pr1[tig]);
            a[2] = __float_as_uint(pr0[tig + 4]);
            a[3] = __float_as_uint(pr1[tig + 4]);
            const float* vr0 = &s[OFF_V + (k0 * 8 + tig) * VST + g];
            const float* vr1 = vr0 + 4 * VST;
#pragma unroll
            for (int n0 = 0; n0 < 8; n0++) {
                uint32_t b0 = __float_as_uint(vr0[n0 * 8]);
                uint32_t b1 = __float_as_uint(vr1[n0 * 8]);
                mma8(oacc[n0], a, b0, b1);
            }
        }
        __syncthreads();   // all warps done with K/V before next stage
    }

    // ---- reduce l across the 4 lanes sharing each row ----
    l0 += __shfl_xor_sync(0xffffffffu, l0, 1);
    l0 += __shfl_xor_sync(0xffffffffu, l0, 2);
    l1 += __shfl_xor_sync(0xffffffffu, l1, 1);
    l1 += __shfl_xor_sync(0xffffffffu, l1, 2);
    const float inv0 = 1.0f / l0;
    const float inv1 = 1.0f / l1;

    // ---- normalize + write O ----
    float* orow0 = out + (size_t)(plane + qg0) * Dd;
    float* orow1 = orow0 + 8 * Dd;
#pragma unroll
    for (int n0 = 0; n0 < 8; n0++) {
        *(float2*)&orow0[n0 * 8 + 2 * tig] =
            make_float2(oacc[n0][0] * inv0, oacc[n0][1] * inv0);
        *(float2*)&orow1[n0 * 8 + 2 * tig] =
            make_float2(oacc[n0][2] * inv1, oacc[n0][3] * inv1);
    }
}

// ---------------------------------------------------------------------------
extern "C" void kernel_launch(void* const* d_in, const int* in_sizes, int n_in,
                              void* d_out, int out_size) {
    const float* q    = (const float*)d_in[0];
    const float* k    = (const float*)d_in[1];
    const float* v    = (const float*)d_in[2];
    const void*  mask = d_in[3];
    const float* taus = (const float*)d_in[4];
    const float* bias = (const float*)d_in[5];
    float*       out  = (float*)d_out;
    (void)in_sizes; (void)n_in; (void)out_size;

    const int smem_bytes = SMEM_FLOATS * 4;
    cudaFuncSetAttribute(attn_kernel, cudaFuncAttributeMaxDynamicSharedMemorySize,
                         smem_bytes);

    detect_mask_kernel<<<1, 256>>>((const unsigned int*)mask);
    expand_mask_kernel<<<(Bb * Ss + 255) / 256, 256>>>(mask);

    dim3 grid(Ss / BM, Hh, Bb);
    attn_kernel<<<grid, NTHREADS, smem_bytes>>>(q, k, v, taus, bias, out);
}

// round 5
// speedup vs baseline: 3.5740x; 1.6204x over previous
#include <cuda_runtime.h>
#include <float.h>
#include <stdint.h>

#define Bb 2
#define Hh 16
#define Ss 2048
#define Dd 64
#define BM 128          // query rows per CTA (8 warps x 16 rows)
#define BN 64           // key tile
#define NTHREADS 256
#define NTILES (Ss / BN)   // 32

// ---- shared memory layout (float offsets) ----
#define KST 68
#define VST 72
#define OFF_MASK 0                      // [2048] additive mask row
#define OFF_K    2048                   // [64][68] K tile (padded)
#define OFF_V    (OFF_K + 64 * KST)     // [64][72] V tile (padded)
#define SMEM_FLOATS (OFF_V + 64 * VST)  // 11008 floats = 44032 B

// ---------------------------------------------------------------------------
// tf32 helpers
// ---------------------------------------------------------------------------
__device__ __forceinline__ float rna(float x) {
    uint32_t u;
    asm("cvt.rna.tf32.f32 %0, %1;" : "=r"(u) : "f"(x));
    return __uint_as_float(u);
}
__device__ __forceinline__ float4 rna4(float4 t) {
    return make_float4(rna(t.x), rna(t.y), rna(t.z), rna(t.w));
}

// D += A*B, m16n8k8 tf32 (PTX fragment layouts)
__device__ __forceinline__ void mma8(float* d, const uint32_t* a,
                                     uint32_t b0, uint32_t b1) {
    asm volatile(
        "mma.sync.aligned.m16n8k8.row.col.f32.tf32.tf32.f32 "
        "{%0,%1,%2,%3},{%4,%5,%6,%7},{%8,%9},{%0,%1,%2,%3};"
        : "+f"(d[0]), "+f"(d[1]), "+f"(d[2]), "+f"(d[3])
        : "r"(a[0]), "r"(a[1]), "r"(a[2]), "r"(a[3]), "r"(b0), "r"(b1));
}

// ---------------------------------------------------------------------------
// Mask prepass (jax bool may be byte-bool or int32; detect then expand)
// ---------------------------------------------------------------------------
__device__ int   g_mask_is_i32;
__device__ float g_maskadd[Bb * Ss];

__global__ void detect_mask_kernel(const unsigned int* __restrict__ mask_w) {
    __shared__ int bad;
    if (threadIdx.x == 0) bad = 0;
    __syncthreads();
    for (int idx = threadIdx.x; idx < (Bb * Ss) / 4; idx += blockDim.x)
        if (mask_w[idx] > 1u) bad = 1;
    __syncthreads();
    if (threadIdx.x == 0) g_mask_is_i32 = bad ? 0 : 1;
}
__global__ void expand_mask_kernel(const void* __restrict__ mask) {
    int idx = blockIdx.x * blockDim.x + threadIdx.x;
    if (idx >= Bb * Ss) return;
    int mval = g_mask_is_i32 ? ((const int*)mask)[idx]
                             : (int)((const unsigned char*)mask)[idx];
    g_maskadd[idx] = mval ? 0.0f : -FLT_MAX;
}

// ---------------------------------------------------------------------------
// Main attention kernel: streaming S, shuffle-based P conversion, 2 CTAs/SM
// ---------------------------------------------------------------------------
__global__ void __launch_bounds__(NTHREADS, 2)
attn_kernel(const float* __restrict__ q,
            const float* __restrict__ k,
            const float* __restrict__ v,
            const float* __restrict__ taus,
            const float* __restrict__ bias,
            float* __restrict__ out)
{
    extern __shared__ float s[];

    const int tid  = threadIdx.x;
    const int wid  = tid >> 5;
    const int lane = tid & 31;
    const int g    = lane >> 2;    // groupID (row within fragment)
    const int tig  = lane & 3;     // threadID_in_group
    const int odd  = tig & 1;
    const int sl   = (lane & ~3) | (tig >> 1);   // shuffle src for col=tig
    const int sl2  = sl + 2;                     // shuffle src for col=tig+4

    const int itile = blockIdx.x;
    const int h     = blockIdx.y;
    const int b     = blockIdx.z;

    const int   plane = (b * Hh + h) * Ss;
    const float tau   = taus[h];
    const int   rowb  = wid * 16;              // warp's first local row
    const int   qg0   = itile * BM + rowb + g; // global row for g-half

    // ---- stage mask row ----
    {
        const float* madd = g_maskadd + b * Ss;
        for (int x = tid; x < Ss; x += NTHREADS) s[OFF_MASK + x] = madd[x];
    }

    // ---- load Q fragments directly from gmem (one-time, tf32-rounded) ----
    uint32_t qf[8][4];
    {
        const float* q0 = q + (size_t)(plane + qg0) * Dd;
        const float* q1 = q0 + 8 * Dd;
#pragma unroll
        for (int k0 = 0; k0 < 8; k0++) {
            qf[k0][0] = __float_as_uint(rna(q0[k0 * 8 + tig]));
            qf[k0][1] = __float_as_uint(rna(q1[k0 * 8 + tig]));
            qf[k0][2] = __float_as_uint(rna(q0[k0 * 8 + tig + 4]));
            qf[k0][3] = __float_as_uint(rna(q1[k0 * 8 + tig + 4]));
        }
    }

    float oacc[8][4];
#pragma unroll
    for (int n0 = 0; n0 < 8; n0++)
#pragma unroll
        for (int x = 0; x < 4; x++) oacc[n0][x] = 0.f;
    float l0 = 0.f, l1 = 0.f;

    const float4* ksrc = (const float4*)(k + (size_t)plane * Dd);
    const float4* vsrc = (const float4*)(v + (size_t)plane * Dd);
    const float* brow0 = bias + ((size_t)b * Ss + qg0) * Ss;
    const float* brow1 = brow0 + 8 * Ss;

    for (int t = 0; t < NTILES; t++) {
        const int j0 = t * BN;

        // ---- stage K,V tiles (tf32-rounded, padded strides) ----
        for (int idx = tid; idx < BN * (Dd / 4); idx += NTHREADS) {
            int row = idx >> 4, c4 = idx & 15;
            *(float4*)&s[OFF_K + row * KST + c4 * 4] = rna4(ksrc[j0 * 16 + idx]);
            *(float4*)&s[OFF_V + row * VST + c4 * 4] = rna4(vsrc[j0 * 16 + idx]);
        }
        __syncthreads();

        // ---- stream over 8-key groups ----
#pragma unroll
        for (int kg = 0; kg < 8; kg++) {
            // MMA1: S(16x8) = Q(16x64) @ K_kg^T
            float sa[4] = {0.f, 0.f, 0.f, 0.f};
            const float* krow = &s[OFF_K + (kg * 8 + g) * KST];
#pragma unroll
            for (int k0 = 0; k0 < 8; k0++) {
                uint32_t b0 = __float_as_uint(krow[k0 * 8 + tig]);
                uint32_t b1 = __float_as_uint(krow[k0 * 8 + tig + 4]);
                mma8(sa, qf[k0], b0, b1);
            }

            // softmax: scale + mask + tau*bias + exp
            const int jl  = kg * 8 + tig * 2;
            const int jgl = j0 + jl;
            float2 mk  = *(const float2*)&s[OFF_MASK + jgl];
            float2 bi0 = *(const float2*)&brow0[jgl];
            float2 bi1 = *(const float2*)&brow1[jgl];
            // masked: x*0.125 + (-FLT_MAX) -> -FLT_MAX; __expf(-FLT_MAX) == 0.
            float p0 = __expf(fmaf(sa[0], 0.125f, mk.x) - tau * bi0.x);
            float p1 = __expf(fmaf(sa[1], 0.125f, mk.y) - tau * bi0.y);
            float p2 = __expf(fmaf(sa[2], 0.125f, mk.x) - tau * bi1.x);
            float p3 = __expf(fmaf(sa[3], 0.125f, mk.y) - tau * bi1.y);
            l0 += p0 + p1;
            l1 += p2 + p3;
            p0 = rna(p0); p1 = rna(p1); p2 = rna(p2); p3 = rna(p3);

            // D-frag (cols 2t,2t+1) -> A-frag (cols t,t+4) via shuffles
            uint32_t a[4];
            {
                float e, o;
                e = __shfl_sync(0xffffffffu, p0, sl);
                o = __shfl_sync(0xffffffffu, p1, sl);
                a[0] = __float_as_uint(odd ? o : e);
                e = __shfl_sync(0xffffffffu, p2, sl);
                o = __shfl_sync(0xffffffffu, p3, sl);
                a[1] = __float_as_uint(odd ? o : e);
                e = __shfl_sync(0xffffffffu, p0, sl2);
                o = __shfl_sync(0xffffffffu, p1, sl2);
                a[2] = __float_as_uint(odd ? o : e);
                e = __shfl_sync(0xffffffffu, p2, sl2);
                o = __shfl_sync(0xffffffffu, p3, sl2);
                a[3] = __float_as_uint(odd ? o : e);
            }

            // MMA2: O(16x64) += P_kg(16x8) @ V_kg(8x64)
            const float* vr0 = &s[OFF_V + (kg * 8 + tig) * VST + g];
            const float* vr1 = vr0 + 4 * VST;
#pragma unroll
            for (int n0 = 0; n0 < 8; n0++) {
                uint32_t b0 = __float_as_uint(vr0[n0 * 8]);
                uint32_t b1 = __float_as_uint(vr1[n0 * 8]);
                mma8(oacc[n0], a, b0, b1);
            }
        }
        __syncthreads();   // all warps done with K/V before restage
    }

    // ---- reduce l across the 4 lanes sharing each row ----
    l0 += __shfl_xor_sync(0xffffffffu, l0, 1);
    l0 += __shfl_xor_sync(0xffffffffu, l0, 2);
    l1 += __shfl_xor_sync(0xffffffffu, l1, 1);
    l1 += __shfl_xor_sync(0xffffffffu, l1, 2);
    const float inv0 = 1.0f / l0;
    const float inv1 = 1.0f / l1;

    // ---- normalize + write O ----
    float* orow0 = out + (size_t)(plane + qg0) * Dd;
    float* orow1 = orow0 + 8 * Dd;
#pragma unroll
    for (int n0 = 0; n0 < 8; n0++) {
        *(float2*)&orow0[n0 * 8 + 2 * tig] =
            make_float2(oacc[n0][0] * inv0, oacc[n0][1] * inv0);
        *(float2*)&orow1[n0 * 8 + 2 * tig] =
            make_float2(oacc[n0][2] * inv1, oacc[n0][3] * inv1);
    }
}

// ---------------------------------------------------------------------------
extern "C" void kernel_launch(void* const* d_in, const int* in_sizes, int n_in,
                              void* d_out, int out_size) {
    const float* q    = (const float*)d_in[0];
    const float* k    = (const float*)d_in[1];
    const float* v    = (const float*)d_in[2];
    const void*  mask = d_in[3];
    const float* taus = (const float*)d_in[4];
    const float* bias = (const float*)d_in[5];
    float*       out  = (float*)d_out;
    (void)in_sizes; (void)n_in; (void)out_size;

    const int smem_bytes = SMEM_FLOATS * 4;
    cudaFuncSetAttribute(attn_kernel, cudaFuncAttributeMaxDynamicSharedMemorySize,
                         smem_bytes);

    detect_mask_kernel<<<1, 256>>>((const unsigned int*)mask);
    expand_mask_kernel<<<(Bb * Ss + 255) / 256, 256>>>(mask);

    dim3 grid(Ss / BM, Hh, Bb);
    attn_kernel<<<grid, NTHREADS, smem_bytes>>>(q, k, v, taus, bias, out);
}

// round 6
// speedup vs baseline: 3.9563x; 1.1069x over previous
#include <cuda_runtime.h>
#include <float.h>
#include <stdint.h>

#define Bb 2
#define Hh 16
#define Ss 2048
#define Dd 64
#define BM 128          // query rows per CTA (8 warps x 16 rows)
#define BN 64           // key tile
#define NTHREADS 256
#define NTILES (Ss / BN)   // 32

// ---- shared memory layout (float offsets) ----
// K/V tiles stored FRAGMENT-PACKED: [kg (8)][lane (32)][20]  (16 used + 4 pad)
// lane stride 20 floats -> LDS.128 at lane*20+{0,4,8,12} is bank-conflict-free.
#define LST 20
#define KGSZ (32 * LST)                  // 640 floats per key-group
#define OFF_MASK 0                       // [2048] additive mask row
#define OFF_K    2048                    // 8*640 = 5120
#define OFF_V    (OFF_K + 8 * KGSZ)      // 7168: 8*640 = 5120
#define SMEM_FLOATS (OFF_V + 8 * KGSZ)   // 12288 floats = 49152 B

// ---------------------------------------------------------------------------
// tf32 helpers
// ---------------------------------------------------------------------------
__device__ __forceinline__ float rna(float x) {
    uint32_t u;
    asm("cvt.rna.tf32.f32 %0, %1;" : "=r"(u) : "f"(x));
    return __uint_as_float(u);
}

// D += A*B, m16n8k8 tf32 (PTX fragment layouts)
__device__ __forceinline__ void mma8(float* d, const uint32_t* a,
                                     uint32_t b0, uint32_t b1) {
    asm volatile(
        "mma.sync.aligned.m16n8k8.row.col.f32.tf32.tf32.f32 "
        "{%0,%1,%2,%3},{%4,%5,%6,%7},{%8,%9},{%0,%1,%2,%3};"
        : "+f"(d[0]), "+f"(d[1]), "+f"(d[2]), "+f"(d[3])
        : "r"(a[0]), "r"(a[1]), "r"(a[2]), "r"(a[3]), "r"(b0), "r"(b1));
}

// ---------------------------------------------------------------------------
// Mask prepass (jax bool may be byte-bool or int32; detect then expand)
// ---------------------------------------------------------------------------
__device__ int   g_mask_is_i32;
__device__ float g_maskadd[Bb * Ss];

__global__ void detect_mask_kernel(const unsigned int* __restrict__ mask_w) {
    __shared__ int bad;
    if (threadIdx.x == 0) bad = 0;
    __syncthreads();
    for (int idx = threadIdx.x; idx < (Bb * Ss) / 4; idx += blockDim.x)
        if (mask_w[idx] > 1u) bad = 1;
    __syncthreads();
    if (threadIdx.x == 0) g_mask_is_i32 = bad ? 0 : 1;
}
__global__ void expand_mask_kernel(const void* __restrict__ mask) {
    int idx = blockIdx.x * blockDim.x + threadIdx.x;
    if (idx >= Bb * Ss) return;
    int mval = g_mask_is_i32 ? ((const int*)mask)[idx]
                             : (int)((const unsigned char*)mask)[idx];
    g_maskadd[idx] = mval ? 0.0f : -FLT_MAX;
}

// ---------------------------------------------------------------------------
// Main attention kernel: fragment-packed smem, streaming S, shuffle P-convert
// ---------------------------------------------------------------------------
__global__ void __launch_bounds__(NTHREADS, 2)
attn_kernel(const float* __restrict__ q,
            const float* __restrict__ k,
            const float* __restrict__ v,
            const float* __restrict__ taus,
            const float* __restrict__ bias,
            float* __restrict__ out)
{
    extern __shared__ float s[];

    const int tid  = threadIdx.x;
    const int wid  = tid >> 5;
    const int lane = tid & 31;
    const int g    = lane >> 2;    // groupID (row within fragment)
    const int tig  = lane & 3;     // threadID_in_group
    const int odd  = tig & 1;
    const int sl   = (lane & ~3) | (tig >> 1);   // shuffle src for col=tig
    const int sl2  = sl + 2;                     // shuffle src for col=tig+4

    const int itile = blockIdx.x;
    const int h     = blockIdx.y;
    const int b     = blockIdx.z;

    const int   plane = (b * Hh + h) * Ss;
    const float tau   = taus[h];
    const int   rowb  = wid * 16;              // warp's first local row
    const int   qg0   = itile * BM + rowb + g; // global row for g-half

    // ---- stage mask row ----
    {
        const float* madd = g_maskadd + b * Ss;
        for (int x = tid; x < Ss; x += NTHREADS) s[OFF_MASK + x] = madd[x];
    }

    // ---- load Q fragments directly from gmem (one-time, tf32-rounded) ----
    uint32_t qf[8][4];
    {
        const float* q0 = q + (size_t)(plane + qg0) * Dd;
        const float* q1 = q0 + 8 * Dd;
#pragma unroll
        for (int k0 = 0; k0 < 8; k0++) {
            qf[k0][0] = __float_as_uint(rna(q0[k0 * 8 + tig]));
            qf[k0][1] = __float_as_uint(rna(q1[k0 * 8 + tig]));
            qf[k0][2] = __float_as_uint(rna(q0[k0 * 8 + tig + 4]));
            qf[k0][3] = __float_as_uint(rna(q1[k0 * 8 + tig + 4]));
        }
    }

    float oacc[8][4];
#pragma unroll
    for (int n0 = 0; n0 < 8; n0++)
#pragma unroll
        for (int x = 0; x < 4; x++) oacc[n0][x] = 0.f;
    float l0 = 0.f, l1 = 0.f;

    const float4* ksrc = (const float4*)(k + (size_t)plane * Dd);
    const float4* vsrc = (const float4*)(v + (size_t)plane * Dd);
    const float* brow0 = bias + ((size_t)b * Ss + qg0) * Ss;
    const float* brow1 = brow0 + 8 * Ss;

    for (int t = 0; t < NTILES; t++) {
        const int j0 = t * BN;

        // ---- stage K,V into fragment-packed layout (tf32-rounded) ----
        // K element [key][d] -> lane 4*(key&7)+(d&3), slot 2*(d>>3)+((d>>2)&1)
        // V element [row][c] -> lane 4*(c&7)+(row&3),  slot 2*(c>>3)+((row>>2)&1)
#pragma unroll
        for (int it = 0; it < 4; it++) {
            const int idx = tid + it * NTHREADS;     // 0..1023
            const int row = idx >> 4;
            const int c   = (idx & 15) * 4;
            const int kg  = row >> 3;

            float4 kv = ksrc[j0 * 16 + idx];
            {
                const int gk = row & 7, k0 = c >> 3, hf = (c >> 2) & 1;
                float* kb = &s[OFF_K + kg * KGSZ + gk * (4 * LST) + k0 * 2 + hf];
                kb[0 * LST] = rna(kv.x);
                kb[1 * LST] = rna(kv.y);
                kb[2 * LST] = rna(kv.z);
                kb[3 * LST] = rna(kv.w);
            }
            float4 vv = vsrc[j0 * 16 + idx];
            {
                const int tv = row & 3, hv = (row >> 2) & 1, n0 = c >> 3;
                float* vb = &s[OFF_V + kg * KGSZ + (c & 7) * (4 * LST)
                               + tv * LST + n0 * 2 + hv];
                vb[0 * (4 * LST)] = rna(vv.x);
                vb[1 * (4 * LST)] = rna(vv.y);
                vb[2 * (4 * LST)] = rna(vv.z);
                vb[3 * (4 * LST)] = rna(vv.w);
            }
        }
        __syncthreads();

        // ---- stream over 8-key groups ----
#pragma unroll
        for (int kg = 0; kg < 8; kg++) {
            // K fragments: 4x LDS.128, conflict-free (stride 20 floats/lane)
            float kfr[16];
            {
                const float4* kp = (const float4*)&s[OFF_K + kg * KGSZ + lane * LST];
                *(float4*)&kfr[0]  = kp[0];
                *(float4*)&kfr[4]  = kp[1];
                *(float4*)&kfr[8]  = kp[2];
                *(float4*)&kfr[12] = kp[3];
            }

            // MMA1: S(16x8) = Q(16x64) @ K_kg^T
            float sa[4] = {0.f, 0.f, 0.f, 0.f};
#pragma unroll
            for (int k0 = 0; k0 < 8; k0++)
                mma8(sa, qf[k0], __float_as_uint(kfr[2 * k0]),
                     __float_as_uint(kfr[2 * k0 + 1]));

            // softmax: scale + mask + tau*bias + exp
            const int jl  = kg * 8 + tig * 2;
            const int jgl = j0 + jl;
            float2 mk  = *(const float2*)&s[OFF_MASK + jgl];
            float2 bi0 = *(const float2*)&brow0[jgl];
            float2 bi1 = *(const float2*)&brow1[jgl];
            // masked: x*0.125 + (-FLT_MAX) -> -FLT_MAX; __expf(-FLT_MAX) == 0.
            float p0 = __expf(fmaf(sa[0], 0.125f, mk.x) - tau * bi0.x);
            float p1 = __expf(fmaf(sa[1], 0.125f, mk.y) - tau * bi0.y);
            float p2 = __expf(fmaf(sa[2], 0.125f, mk.x) - tau * bi1.x);
            float p3 = __expf(fmaf(sa[3], 0.125f, mk.y) - tau * bi1.y);
            l0 += p0 + p1;
            l1 += p2 + p3;
            p0 = rna(p0); p1 = rna(p1); p2 = rna(p2); p3 = rna(p3);

            // D-frag (cols 2t,2t+1) -> A-frag (cols t,t+4) via shuffles
            uint32_t a[4];
            {
                float e, o;
                e = __shfl_sync(0xffffffffu, p0, sl);
                o = __shfl_sync(0xffffffffu, p1, sl);
                a[0] = __float_as_uint(odd ? o : e);
                e = __shfl_sync(0xffffffffu, p2, sl);
                o = __shfl_sync(0xffffffffu, p3, sl);
                a[1] = __float_as_uint(odd ? o : e);
                e = __shfl_sync(0xffffffffu, p0, sl2);
                o = __shfl_sync(0xffffffffu, p1, sl2);
                a[2] = __float_as_uint(odd ? o : e);
                e = __shfl_sync(0xffffffffu, p2, sl2);
                o = __shfl_sync(0xffffffffu, p3, sl2);
                a[3] = __float_as_uint(odd ? o : e);
            }

            // V fragments: 4x LDS.128, conflict-free
            float vfr[16];
            {
                const float4* vp = (const float4*)&s[OFF_V + kg * KGSZ + lane * LST];
                *(float4*)&vfr[0]  = vp[0];
                *(float4*)&vfr[4]  = vp[1];
                *(float4*)&vfr[8]  = vp[2];
                *(float4*)&vfr[12] = vp[3];
            }

            // MMA2: O(16x64) += P_kg(16x8) @ V_kg(8x64)
#pragma unroll
            for (int n0 = 0; n0 < 8; n0++)
                mma8(oacc[n0], a, __float_as_uint(vfr[2 * n0]),
                     __float_as_uint(vfr[2 * n0 + 1]));
        }
        __syncthreads();   // all warps done with K/V before restage
    }

    // ---- reduce l across the 4 lanes sharing each row ----
    l0 += __shfl_xor_sync(0xffffffffu, l0, 1);
    l0 += __shfl_xor_sync(0xffffffffu, l0, 2);
    l1 += __shfl_xor_sync(0xffffffffu, l1, 1);
    l1 += __shfl_xor_sync(0xffffffffu, l1, 2);
    const float inv0 = 1.0f / l0;
    const float inv1 = 1.0f / l1;

    // ---- normalize + write O ----
    float* orow0 = out + (size_t)(plane + qg0) * Dd;
    float* orow1 = orow0 + 8 * Dd;
#pragma unroll
    for (int n0 = 0; n0 < 8; n0++) {
        *(float2*)&orow0[n0 * 8 + 2 * tig] =
            make_float2(oacc[n0][0] * inv0, oacc[n0][1] * inv0);
        *(float2*)&orow1[n0 * 8 + 2 * tig] =
            make_float2(oacc[n0][2] * inv1, oacc[n0][3] * inv1);
    }
}

// ---------------------------------------------------------------------------
extern "C" void kernel_launch(void* const* d_in, const int* in_sizes, int n_in,
                              void* d_out, int out_size) {
    const float* q    = (const float*)d_in[0];
    const float* k    = (const float*)d_in[1];
    const float* v    = (const float*)d_in[2];
    const void*  mask = d_in[3];
    const float* taus = (const float*)d_in[4];
    const float* bias = (const float*)d_in[5];
    float*       out  = (float*)d_out;
    (void)in_sizes; (void)n_in; (void)out_size;

    const int smem_bytes = SMEM_FLOATS * 4;
    cudaFuncSetAttribute(attn_kernel, cudaFuncAttributeMaxDynamicSharedMemorySize,
                         smem_bytes);

    detect_mask_kernel<<<1, 256>>>((const unsigned int*)mask);
    expand_mask_kernel<<<(Bb * Ss + 255) / 256, 256>>>(mask);

    dim3 grid(Ss / BM, Hh, Bb);
    attn_kernel<<<grid, NTHREADS, smem_bytes>>>(q, k, v, taus, bias, out);
}

// round 7
// speedup vs baseline: 4.2146x; 1.0653x over previous
#include <cuda_runtime.h>
#include <float.h>
#include <stdint.h>

#define Bb 2
#define Hh 16
#define Ss 2048
#define Dd 64
#define BM 128          // query rows per CTA (8 warps x 16 rows)
#define BN 64           // key tile
#define NTHREADS 256
#define NTILES (Ss / BN)   // 32

// ---- shared memory layout (float offsets) ----
// K/V tiles stored FRAGMENT-PACKED: [kg (8)][lane (32)][20]  (16 used + 4 pad)
// lane stride 20 floats -> LDS.128 at lane*20+{0,4,8,12} is bank-conflict-free.
#define LST 20
#define KGSZ (32 * LST)                  // 640 floats per key-group
#define OFF_MASK 0                       // [2048] additive mask row
#define OFF_K    2048                    // 8*640 = 5120
#define OFF_V    (OFF_K + 8 * KGSZ)      // 7168: 8*640 = 5120
#define SMEM_FLOATS (OFF_V + 8 * KGSZ)   // 12288 floats = 49152 B

// ---------------------------------------------------------------------------
// tf32 helpers
// ---------------------------------------------------------------------------
__device__ __forceinline__ float rna(float x) {
    uint32_t u;
    asm("cvt.rna.tf32.f32 %0, %1;" : "=r"(u) : "f"(x));
    return __uint_as_float(u);
}

// D += A*B, m16n8k8 tf32 (PTX fragment layouts)
__device__ __forceinline__ void mma8(float* d, const uint32_t* a,
                                     uint32_t b0, uint32_t b1) {
    asm volatile(
        "mma.sync.aligned.m16n8k8.row.col.f32.tf32.tf32.f32 "
        "{%0,%1,%2,%3},{%4,%5,%6,%7},{%8,%9},{%0,%1,%2,%3};"
        : "+f"(d[0]), "+f"(d[1]), "+f"(d[2]), "+f"(d[3])
        : "r"(a[0]), "r"(a[1]), "r"(a[2]), "r"(a[3]), "r"(b0), "r"(b1));
}

// ---------------------------------------------------------------------------
// Mask prepass (jax bool may be byte-bool or int32; detect then expand)
// ---------------------------------------------------------------------------
__device__ int   g_mask_is_i32;
__device__ float g_maskadd[Bb * Ss];

__global__ void detect_mask_kernel(const unsigned int* __restrict__ mask_w) {
    __shared__ int bad;
    if (threadIdx.x == 0) bad = 0;
    __syncthreads();
    for (int idx = threadIdx.x; idx < (Bb * Ss) / 4; idx += blockDim.x)
        if (mask_w[idx] > 1u) bad = 1;
    __syncthreads();
    if (threadIdx.x == 0) g_mask_is_i32 = bad ? 0 : 1;
}
__global__ void expand_mask_kernel(const void* __restrict__ mask) {
    int idx = blockIdx.x * blockDim.x + threadIdx.x;
    if (idx >= Bb * Ss) return;
    int mval = g_mask_is_i32 ? ((const int*)mask)[idx]
                             : (int)((const unsigned char*)mask)[idx];
    g_maskadd[idx] = mval ? 0.0f : -FLT_MAX;
}

// ---------------------------------------------------------------------------
// Main attention kernel: fragment-packed smem, permuted-V (no shuffles),
// software-pipelined K/V staging, 2 CTAs/SM.
// ---------------------------------------------------------------------------
__global__ void __launch_bounds__(NTHREADS, 2)
attn_kernel(const float* __restrict__ q,
            const float* __restrict__ k,
            const float* __restrict__ v,
            const float* __restrict__ taus,
            const float* __restrict__ bias,
            float* __restrict__ out)
{
    extern __shared__ float s[];

    const int tid  = threadIdx.x;
    const int wid  = tid >> 5;
    const int lane = tid & 31;
    const int g    = lane >> 2;    // groupID (row within fragment)
    const int tig  = lane & 3;     // threadID_in_group

    const int itile = blockIdx.x;
    const int h     = blockIdx.y;
    const int b     = blockIdx.z;

    const int   plane = (b * Hh + h) * Ss;
    const float tau   = taus[h];
    const int   rowb  = wid * 16;              // warp's first local row
    const int   qg0   = itile * BM + rowb + g; // global row for g-half

    // ---- stage mask row ----
    {
        const float* madd = g_maskadd + b * Ss;
        for (int x = tid; x < Ss; x += NTHREADS) s[OFF_MASK + x] = madd[x];
    }

    // ---- load Q fragments directly from gmem (one-time, tf32-rounded) ----
    uint32_t qf[8][4];
    {
        const float* q0 = q + (size_t)(plane + qg0) * Dd;
        const float* q1 = q0 + 8 * Dd;
#pragma unroll
        for (int k0 = 0; k0 < 8; k0++) {
            qf[k0][0] = __float_as_uint(rna(q0[k0 * 8 + tig]));
            qf[k0][1] = __float_as_uint(rna(q1[k0 * 8 + tig]));
            qf[k0][2] = __float_as_uint(rna(q0[k0 * 8 + tig + 4]));
            qf[k0][3] = __float_as_uint(rna(q1[k0 * 8 + tig + 4]));
        }
    }

    float oacc[8][4];
#pragma unroll
    for (int n0 = 0; n0 < 8; n0++)
#pragma unroll
        for (int x = 0; x < 4; x++) oacc[n0][x] = 0.f;
    float l0 = 0.f, l1 = 0.f;

    const float4* ksrc = (const float4*)(k + (size_t)plane * Dd);
    const float4* vsrc = (const float4*)(v + (size_t)plane * Dd);
    const float* brow0 = bias + ((size_t)b * Ss + qg0) * Ss;
    const float* brow1 = brow0 + 8 * Ss;

    // ---- software pipeline: prefetch tile 0 into registers ----
    float4 kbuf[4], vbuf[4];
#pragma unroll
    for (int it = 0; it < 4; it++) {
        kbuf[it] = ksrc[tid + it * NTHREADS];
        vbuf[it] = vsrc[tid + it * NTHREADS];
    }

    for (int t = 0; t < NTILES; t++) {
        // ---- scatter buffered K,V into fragment-packed layout ----
        // K elem [key][d] -> lane 4*(key&7)+(d&3), slot 2*(d>>3)+((d>>2)&1)
        // V rows PERMUTED: actual row r -> virtual vk = (r&1)? (r>>1)+4 : r>>1
        //   so feeding the MMA1 D-fragment directly as MMA2's A-fragment sums
        //   the matching key for every virtual k slot (no shuffles needed).
#pragma unroll
        for (int it = 0; it < 4; it++) {
            const int idx = tid + it * NTHREADS;     // 0..1023
            const int row = idx >> 4;
            const int c   = (idx & 15) * 4;
            const int kg  = row >> 3;
            const int r   = row & 7;

            {
                const int k0 = c >> 3, hf = (c >> 2) & 1;
                float* kb = &s[OFF_K + kg * KGSZ + r * (4 * LST) + k0 * 2 + hf];
                kb[0 * LST] = rna(kbuf[it].x);
                kb[1 * LST] = rna(kbuf[it].y);
                kb[2 * LST] = rna(kbuf[it].z);
                kb[3 * LST] = rna(kbuf[it].w);
            }
            {
                const int vk = (r & 1) ? ((r >> 1) + 4) : (r >> 1);
                const int tv = vk & 3, hv = (vk >> 2) & 1, n0 = c >> 3;
                float* vb = &s[OFF_V + kg * KGSZ + (c & 7) * (4 * LST)
                               + tv * LST + n0 * 2 + hv];
                vb[0 * (4 * LST)] = rna(vbuf[it].x);
                vb[1 * (4 * LST)] = rna(vbuf[it].y);
                vb[2 * (4 * LST)] = rna(vbuf[it].z);
                vb[3 * (4 * LST)] = rna(vbuf[it].w);
            }
        }
        __syncthreads();

        // ---- prefetch NEXT tile (latency hidden behind compute below) ----
        if (t + 1 < NTILES) {
            const int base = (t + 1) * BN * 16;   // float4 index
#pragma unroll
            for (int it = 0; it < 4; it++) {
                kbuf[it] = ksrc[base + tid + it * NTHREADS];
                vbuf[it] = vsrc[base + tid + it * NTHREADS];
            }
        }

        const int j0 = t * BN;

        // ---- stream over 8-key groups ----
#pragma unroll
        for (int kg = 0; kg < 8; kg++) {
            // K fragments: 4x LDS.128, conflict-free (stride 20 floats/lane)
            float kfr[16];
            {
                const float4* kp = (const float4*)&s[OFF_K + kg * KGSZ + lane * LST];
                *(float4*)&kfr[0]  = kp[0];
                *(float4*)&kfr[4]  = kp[1];
                *(float4*)&kfr[8]  = kp[2];
                *(float4*)&kfr[12] = kp[3];
            }

            // MMA1: S(16x8) = Q(16x64) @ K_kg^T
            float sa[4] = {0.f, 0.f, 0.f, 0.f};
#pragma unroll
            for (int k0 = 0; k0 < 8; k0++)
                mma8(sa, qf[k0], __float_as_uint(kfr[2 * k0]),
                     __float_as_uint(kfr[2 * k0 + 1]));

            // softmax: scale + mask + tau*bias + exp
            const int jl  = kg * 8 + tig * 2;
            const int jgl = j0 + jl;
            float2 mk  = *(const float2*)&s[OFF_MASK + jgl];
            float2 bi0 = *(const float2*)&brow0[jgl];
            float2 bi1 = *(const float2*)&brow1[jgl];
            // masked: x*0.125 + (-FLT_MAX) -> -FLT_MAX; __expf(-FLT_MAX) == 0.
            float p0 = __expf(fmaf(sa[0], 0.125f, mk.x) - tau * bi0.x);
            float p1 = __expf(fmaf(sa[1], 0.125f, mk.y) - tau * bi0.y);
            float p2 = __expf(fmaf(sa[2], 0.125f, mk.x) - tau * bi1.x);
            float p3 = __expf(fmaf(sa[3], 0.125f, mk.y) - tau * bi1.y);
            l0 += p0 + p1;
            l1 += p2 + p3;

            // D-fragment used directly as A-fragment (V rows pre-permuted):
            // a = { P[g][2t], P[g+8][2t], P[g][2t+1], P[g+8][2t+1] }
            uint32_t a[4];
            a[0] = __float_as_uint(rna(p0));
            a[1] = __float_as_uint(rna(p2));
            a[2] = __float_as_uint(rna(p1));
            a[3] = __float_as_uint(rna(p3));

            // V fragments: 4x LDS.128, conflict-free
            float vfr[16];
            {
                const float4* vp = (const float4*)&s[OFF_V + kg * KGSZ + lane * LST];
                *(float4*)&vfr[0]  = vp[0];
                *(float4*)&vfr[4]  = vp[1];
                *(float4*)&vfr[8]  = vp[2];
                *(float4*)&vfr[12] = vp[3];
            }

            // MMA2: O(16x64) += P_kg(16x8) @ V_kg(8x64)
#pragma unroll
            for (int n0 = 0; n0 < 8; n0++)
                mma8(oacc[n0], a, __float_as_uint(vfr[2 * n0]),
                     __float_as_uint(vfr[2 * n0 + 1]));
        }
        __syncthreads();   // all warps done with K/V before restage
    }

    // ---- reduce l across the 4 lanes sharing each row ----
    l0 += __shfl_xor_sync(0xffffffffu, l0, 1);
    l0 += __shfl_xor_sync(0xffffffffu, l0, 2);
    l1 += __shfl_xor_sync(0xffffffffu, l1, 1);
    l1 += __shfl_xor_sync(0xffffffffu, l1, 2);
    const float inv0 = 1.0f / l0;
    const float inv1 = 1.0f / l1;

    // ---- normalize + write O ----
    float* orow0 = out + (size_t)(plane + qg0) * Dd;
    float* orow1 = orow0 + 8 * Dd;
#pragma unroll
    for (int n0 = 0; n0 < 8; n0++) {
        *(float2*)&orow0[n0 * 8 + 2 * tig] =
            make_float2(oacc[n0][0] * inv0, oacc[n0][1] * inv0);
        *(float2*)&orow1[n0 * 8 + 2 * tig] =
            make_float2(oacc[n0][2] * inv1, oacc[n0][3] * inv1);
    }
}

// ---------------------------------------------------------------------------
extern "C" void kernel_launch(void* const* d_in, const int* in_sizes, int n_in,
                              void* d_out, int out_size) {
    const float* q    = (const float*)d_in[0];
    const float* k    = (const float*)d_in[1];
    const float* v    = (const float*)d_in[2];
    const void*  mask = d_in[3];
    const float* taus = (const float*)d_in[4];
    const float* bias = (const float*)d_in[5];
    float*       out  = (float*)d_out;
    (void)in_sizes; (void)n_in; (void)out_size;

    const int smem_bytes = SMEM_FLOATS * 4;
    cudaFuncSetAttribute(attn_kernel, cudaFuncAttributeMaxDynamicSharedMemorySize,
                         smem_bytes);

    detect_mask_kernel<<<1, 256>>>((const unsigned int*)mask);
    expand_mask_kernel<<<(Bb * Ss + 255) / 256, 256>>>(mask);

    dim3 grid(Ss / BM, Hh, Bb);
    attn_kernel<<<grid, NTHREADS, smem_bytes>>>(q, k, v, taus, bias, out);
}

// round 8
// speedup vs baseline: 4.5639x; 1.0829x over previous
#include <cuda_runtime.h>
#include <float.h>
#include <stdint.h>

#define Bb 2
#define Hh 16
#define Ss 2048
#define Dd 64
#define BM 128          // query rows per CTA (4 warps x 32 rows)
#define BN 64           // key tile
#define NTHREADS 128
#define NTILES (Ss / BN)   // 32

// ---- shared memory layout (float offsets) ----
// K/V tiles stored FRAGMENT-PACKED: [kg (8)][lane (32)][20]  (16 used + 4 pad)
// lane stride 20 floats -> LDS.128 at lane*20+{0,4,8,12} is bank-conflict-free.
#define LST 20
#define KGSZ (32 * LST)                  // 640 floats per key-group
#define OFF_MASK 0                       // [2048] additive mask row
#define OFF_K    2048                    // 8*640 = 5120
#define OFF_V    (OFF_K + 8 * KGSZ)      // 7168: 8*640 = 5120
#define SMEM_FLOATS (OFF_V + 8 * KGSZ)   // 12288 floats = 49152 B

// ---------------------------------------------------------------------------
// tf32 helpers
// ---------------------------------------------------------------------------
__device__ __forceinline__ float rna(float x) {
    uint32_t u;
    asm("cvt.rna.tf32.f32 %0, %1;" : "=r"(u) : "f"(x));
    return __uint_as_float(u);
}

// D += A*B, m16n8k8 tf32 (PTX fragment layouts)
__device__ __forceinline__ void mma8(float* d, const uint32_t* a,
                                     uint32_t b0, uint32_t b1) {
    asm volatile(
        "mma.sync.aligned.m16n8k8.row.col.f32.tf32.tf32.f32 "
        "{%0,%1,%2,%3},{%4,%5,%6,%7},{%8,%9},{%0,%1,%2,%3};"
        : "+f"(d[0]), "+f"(d[1]), "+f"(d[2]), "+f"(d[3])
        : "r"(a[0]), "r"(a[1]), "r"(a[2]), "r"(a[3]), "r"(b0), "r"(b1));
}

// ---------------------------------------------------------------------------
// Mask prepass (jax bool may be byte-bool or int32; detect then expand)
// ---------------------------------------------------------------------------
__device__ int   g_mask_is_i32;
__device__ float g_maskadd[Bb * Ss];

__global__ void detect_mask_kernel(const unsigned int* __restrict__ mask_w) {
    __shared__ int bad;
    if (threadIdx.x == 0) bad = 0;
    __syncthreads();
    for (int idx = threadIdx.x; idx < (Bb * Ss) / 4; idx += blockDim.x)
        if (mask_w[idx] > 1u) bad = 1;
    __syncthreads();
    if (threadIdx.x == 0) g_mask_is_i32 = bad ? 0 : 1;
}
__global__ void expand_mask_kernel(const void* __restrict__ mask) {
    int idx = blockIdx.x * blockDim.x + threadIdx.x;
    if (idx >= Bb * Ss) return;
    int mval = g_mask_is_i32 ? ((const int*)mask)[idx]
                             : (int)((const unsigned char*)mask)[idx];
    g_maskadd[idx] = mval ? 0.0f : -FLT_MAX;
}

// ---------------------------------------------------------------------------
// Main attention kernel: 32 rows/warp (2 row-blocks) halves per-warp smem
// re-reads; fragment-packed smem; permuted-V (shuffle-free); prefetch pipeline.
// ---------------------------------------------------------------------------
__global__ void __launch_bounds__(NTHREADS)
attn_kernel(const float* __restrict__ q,
            const float* __restrict__ k,
            const float* __restrict__ v,
            const float* __restrict__ taus,
            const float* __restrict__ bias,
            float* __restrict__ out)
{
    extern __shared__ float s[];

    const int tid  = threadIdx.x;
    const int wid  = tid >> 5;
    const int lane = tid & 31;
    const int g    = lane >> 2;    // groupID (row within fragment)
    const int tig  = lane & 3;     // threadID_in_group

    const int itile = blockIdx.x;
    const int h     = blockIdx.y;
    const int b     = blockIdx.z;

    const int   plane = (b * Hh + h) * Ss;
    const float tau   = taus[h];
    const int   rowb  = wid * 32;               // warp's first local row
    const int   qgA   = itile * BM + rowb + g;  // row-block A, g-half row
    const int   qgB   = qgA + 16;               // row-block B

    // ---- stage mask row ----
    {
        const float* madd = g_maskadd + b * Ss;
        for (int x = tid; x < Ss; x += NTHREADS) s[OFF_MASK + x] = madd[x];
    }

    // ---- load Q fragments for both row-blocks (one-time, tf32-rounded) ----
    uint32_t qfA[8][4], qfB[8][4];
    {
        const float* qa0 = q + (size_t)(plane + qgA) * Dd;
        const float* qa1 = qa0 + 8 * Dd;
        const float* qb0 = q + (size_t)(plane + qgB) * Dd;
        const float* qb1 = qb0 + 8 * Dd;
#pragma unroll
        for (int k0 = 0; k0 < 8; k0++) {
            qfA[k0][0] = __float_as_uint(rna(qa0[k0 * 8 + tig]));
            qfA[k0][1] = __float_as_uint(rna(qa1[k0 * 8 + tig]));
            qfA[k0][2] = __float_as_uint(rna(qa0[k0 * 8 + tig + 4]));
            qfA[k0][3] = __float_as_uint(rna(qa1[k0 * 8 + tig + 4]));
            qfB[k0][0] = __float_as_uint(rna(qb0[k0 * 8 + tig]));
            qfB[k0][1] = __float_as_uint(rna(qb1[k0 * 8 + tig]));
            qfB[k0][2] = __float_as_uint(rna(qb0[k0 * 8 + tig + 4]));
            qfB[k0][3] = __float_as_uint(rna(qb1[k0 * 8 + tig + 4]));
        }
    }

    float oaccA[8][4], oaccB[8][4];
#pragma unroll
    for (int n0 = 0; n0 < 8; n0++)
#pragma unroll
        for (int x = 0; x < 4; x++) { oaccA[n0][x] = 0.f; oaccB[n0][x] = 0.f; }
    float lA0 = 0.f, lA1 = 0.f, lB0 = 0.f, lB1 = 0.f;

    const float4* ksrc = (const float4*)(k + (size_t)plane * Dd);
    const float4* vsrc = (const float4*)(v + (size_t)plane * Dd);
    const float* browA0 = bias + ((size_t)b * Ss + qgA) * Ss;
    const float* browA1 = browA0 + 8 * Ss;
    const float* browB0 = browA0 + 16 * Ss;
    const float* browB1 = browA0 + 24 * Ss;

    // ---- software pipeline: prefetch tile 0 into registers ----
    float4 kbuf[8], vbuf[8];
#pragma unroll
    for (int it = 0; it < 8; it++) {
        kbuf[it] = ksrc[tid + it * NTHREADS];
        vbuf[it] = vsrc[tid + it * NTHREADS];
    }

    for (int t = 0; t < NTILES; t++) {
        // ---- scatter buffered K,V into fragment-packed layout ----
        // K elem [key][d] -> lane 4*(key&7)+(d&3), slot 2*(d>>3)+((d>>2)&1)
        // V rows PERMUTED: actual row r -> virtual vk = (r&1)? (r>>1)+4 : r>>1
        //   so the MMA1 D-fragment feeds MMA2's A-fragment directly.
#pragma unroll
        for (int it = 0; it < 8; it++) {
            const int idx = tid + it * NTHREADS;     // 0..1023
            const int row = idx >> 4;
            const int c   = (idx & 15) * 4;
            const int kg  = row >> 3;
            const int r   = row & 7;

            {
                const int k0 = c >> 3, hf = (c >> 2) & 1;
                float* kb = &s[OFF_K + kg * KGSZ + r * (4 * LST) + k0 * 2 + hf];
                kb[0 * LST] = rna(kbuf[it].x);
                kb[1 * LST] = rna(kbuf[it].y);
                kb[2 * LST] = rna(kbuf[it].z);
                kb[3 * LST] = rna(kbuf[it].w);
            }
            {
                const int vk = (r & 1) ? ((r >> 1) + 4) : (r >> 1);
                const int tv = vk & 3, hv = (vk >> 2) & 1, n0 = c >> 3;
                float* vb = &s[OFF_V + kg * KGSZ + (c & 7) * (4 * LST)
                               + tv * LST + n0 * 2 + hv];
                vb[0 * (4 * LST)] = rna(vbuf[it].x);
                vb[1 * (4 * LST)] = rna(vbuf[it].y);
                vb[2 * (4 * LST)] = rna(vbuf[it].z);
                vb[3 * (4 * LST)] = rna(vbuf[it].w);
            }
        }
        __syncthreads();

        // ---- prefetch NEXT tile (latency hidden behind compute below) ----
        if (t + 1 < NTILES) {
            const int base = (t + 1) * BN * 16;   // float4 index
#pragma unroll
            for (int it = 0; it < 8; it++) {
                kbuf[it] = ksrc[base + tid + it * NTHREADS];
                vbuf[it] = vsrc[base + tid + it * NTHREADS];
            }
        }

        const int j0 = t * BN;

        // ---- stream over 8-key groups ----
#pragma unroll
        for (int kg = 0; kg < 8; kg++) {
            // K fragments: 4x LDS.128, conflict-free (stride 20 floats/lane)
            float kfr[16];
            {
                const float4* kp = (const float4*)&s[OFF_K + kg * KGSZ + lane * LST];
                *(float4*)&kfr[0]  = kp[0];
                *(float4*)&kfr[4]  = kp[1];
                *(float4*)&kfr[8]  = kp[2];
                *(float4*)&kfr[12] = kp[3];
            }

            // MMA1: S(32x8) = Q(32x64) @ K_kg^T  (two row-blocks)
            float saA[4] = {0.f, 0.f, 0.f, 0.f};
            float saB[4] = {0.f, 0.f, 0.f, 0.f};
#pragma unroll
            for (int k0 = 0; k0 < 8; k0++) {
                uint32_t b0 = __float_as_uint(kfr[2 * k0]);
                uint32_t b1 = __float_as_uint(kfr[2 * k0 + 1]);
                mma8(saA, qfA[k0], b0, b1);
                mma8(saB, qfB[k0], b0, b1);
            }

            // softmax: scale + mask + tau*bias + exp (both row-blocks)
            const int jl  = kg * 8 + tig * 2;
            const int jgl = j0 + jl;
            float2 mk = *(const float2*)&s[OFF_MASK + jgl];
            float2 biA0 = *(const float2*)&browA0[jgl];
            float2 biA1 = *(const float2*)&browA1[jgl];
            float2 biB0 = *(const float2*)&browB0[jgl];
            float2 biB1 = *(const float2*)&browB1[jgl];
            // masked: x*0.125 + (-FLT_MAX) -> -FLT_MAX; __expf(-FLT_MAX) == 0.
            float pA0 = __expf(fmaf(saA[0], 0.125f, mk.x) - tau * biA0.x);
            float pA1 = __expf(fmaf(saA[1], 0.125f, mk.y) - tau * biA0.y);
            float pA2 = __expf(fmaf(saA[2], 0.125f, mk.x) - tau * biA1.x);
            float pA3 = __expf(fmaf(saA[3], 0.125f, mk.y) - tau * biA1.y);
            float pB0 = __expf(fmaf(saB[0], 0.125f, mk.x) - tau * biB0.x);
            float pB1 = __expf(fmaf(saB[1], 0.125f, mk.y) - tau * biB0.y);
            float pB2 = __expf(fmaf(saB[2], 0.125f, mk.x) - tau * biB1.x);
            float pB3 = __expf(fmaf(saB[3], 0.125f, mk.y) - tau * biB1.y);
            lA0 += pA0 + pA1;  lA1 += pA2 + pA3;
            lB0 += pB0 + pB1;  lB1 += pB2 + pB3;

            // D-fragment used directly as A-fragment (V rows pre-permuted)
            uint32_t aA[4], aB[4];
            aA[0] = __float_as_uint(rna(pA0));
            aA[1] = __float_as_uint(rna(pA2));
            aA[2] = __float_as_uint(rna(pA1));
            aA[3] = __float_as_uint(rna(pA3));
            aB[0] = __float_as_uint(rna(pB0));
            aB[1] = __float_as_uint(rna(pB2));
            aB[2] = __float_as_uint(rna(pB1));
            aB[3] = __float_as_uint(rna(pB3));

            // V fragments: 4x LDS.128, conflict-free
            float vfr[16];
            {
                const float4* vp = (const float4*)&s[OFF_V + kg * KGSZ + lane * LST];
                *(float4*)&vfr[0]  = vp[0];
                *(float4*)&vfr[4]  = vp[1];
                *(float4*)&vfr[8]  = vp[2];
                *(float4*)&vfr[12] = vp[3];
            }

            // MMA2: O(32x64) += P_kg(32x8) @ V_kg(8x64)
#pragma unroll
            for (int n0 = 0; n0 < 8; n0++) {
                uint32_t b0 = __float_as_uint(vfr[2 * n0]);
                uint32_t b1 = __float_as_uint(vfr[2 * n0 + 1]);
                mma8(oaccA[n0], aA, b0, b1);
                mma8(oaccB[n0], aB, b0, b1);
            }
        }
        __syncthreads();   // all warps done with K/V before restage
    }

    // ---- reduce l across the 4 lanes sharing each row ----
    lA0 += __shfl_xor_sync(0xffffffffu, lA0, 1);
    lA0 += __shfl_xor_sync(0xffffffffu, lA0, 2);
    lA1 += __shfl_xor_sync(0xffffffffu, lA1, 1);
    lA1 += __shfl_xor_sync(0xffffffffu, lA1, 2);
    lB0 += __shfl_xor_sync(0xffffffffu, lB0, 1);
    lB0 += __shfl_xor_sync(0xffffffffu, lB0, 2);
    lB1 += __shfl_xor_sync(0xffffffffu, lB1, 1);
    lB1 += __shfl_xor_sync(0xffffffffu, lB1, 2);
    const float invA0 = 1.0f / lA0;
    const float invA1 = 1.0f / lA1;
    const float invB0 = 1.0f / lB0;
    const float invB1 = 1.0f / lB1;

    // ---- normalize + write O ----
    float* oA0 = out + (size_t)(plane + qgA) * Dd;
    float* oA1 = oA0 + 8 * Dd;
    float* oB0 = out + (size_t)(plane + qgB) * Dd;
    float* oB1 = oB0 + 8 * Dd;
#pragma unroll
    for (int n0 = 0; n0 < 8; n0++) {
        *(float2*)&oA0[n0 * 8 + 2 * tig] =
            make_float2(oaccA[n0][0] * invA0, oaccA[n0][1] * invA0);
        *(float2*)&oA1[n0 * 8 + 2 * tig] =
            make_float2(oaccA[n0][2] * invA1, oaccA[n0][3] * invA1);
        *(float2*)&oB0[n0 * 8 + 2 * tig] =
            make_float2(oaccB[n0][0] * invB0, oaccB[n0][1] * invB0);
        *(float2*)&oB1[n0 * 8 + 2 * tig] =
            make_float2(oaccB[n0][2] * invB1, oaccB[n0][3] * invB1);
    }
}

// ---------------------------------------------------------------------------
extern "C" void kernel_launch(void* const* d_in, const int* in_sizes, int n_in,
                              void* d_out, int out_size) {
    const float* q    = (const float*)d_in[0];
    const float* k    = (const float*)d_in[1];
    const float* v    = (const float*)d_in[2];
    const void*  mask = d_in[3];
    const float* taus = (const float*)d_in[4];
    const float* bias = (const float*)d_in[5];
    float*       out  = (float*)d_out;
    (void)in_sizes; (void)n_in; (void)out_size;

    const int smem_bytes = SMEM_FLOATS * 4;
    cudaFuncSetAttribute(attn_kernel, cudaFuncAttributeMaxDynamicSharedMemorySize,
                         smem_bytes);

    detect_mask_kernel<<<1, 256>>>((const unsigned int*)mask);
    expand_mask_kernel<<<(Bb * Ss + 255) / 256, 256>>>(mask);

    dim3 grid(Ss / BM, Hh, Bb);
    attn_kernel<<<grid, NTHREADS, smem_bytes>>>(q, k, v, taus, bias, out);
}